// round 4
// baseline (speedup 1.0000x reference)
#include <cuda_runtime.h>
#include <math.h>
#include <stddef.h>

#define BB     4
#define SS     1024
#define DMODEL 512
#define HH     8
#define DHEAD  64
#define DFF    2048
#define BHTOT  (BB*HH)          // 32
#define MROWS  (BB*SS)          // 4096
#define NCHUNK 128              // softmax partial chunks per (b,h)

// ---------------- scratch (static device globals: alloc-free) ----------------
__device__ float g_L[(size_t)BHTOT * SS * SS];   // 128 MB logits
__device__ float g_q[MROWS * DMODEL];
__device__ float g_k[MROWS * DMODEL];
__device__ float g_v[MROWS * DMODEL];
__device__ float g_o[MROWS * DMODEL];
__device__ float g_t0[MROWS * DMODEL];           // attn_out / ffn2 out
__device__ float g_out1[MROWS * DMODEL];
__device__ float g_ffn1[MROWS * DFF];
__device__ float g_h[MROWS * DMODEL];            // inter-layer activation
__device__ float g_pm[BHTOT * NCHUNK];
__device__ float g_ps[BHTOT * NCHUNK];
__device__ float g_M[BHTOT];
__device__ float g_scale[BHTOT];
__device__ float g_nz;

// ---------------- count_nonzero(protok[0]) ----------------
__global__ void count_nz_kernel(const int* __restrict__ protok) {
    __shared__ int cnt[256];
    int t = threadIdx.x;
    int c = 0;
    for (int i = t; i < SS; i += 256) c += (protok[i] != 0);
    cnt[t] = c; __syncthreads();
    for (int off = 128; off; off >>= 1) {
        if (t < off) cnt[t] += cnt[t + off];
        __syncthreads();
    }
    if (t == 0) g_nz = (float)cnt[0];
}

// ---------------- generic SGEMM: C = act(A[MxK] * B[KxN] + bias) ----------------
// 128x128 tile, BK=8, 256 threads, 8x8 per thread.
template <bool RELU>
__global__ void __launch_bounds__(256) sgemm128(
    const float* __restrict__ A, const float* __restrict__ Bm,
    const float* __restrict__ bias, float* __restrict__ C,
    int M, int N, int K)
{
    __shared__ float As[8][132];
    __shared__ float Bs[8][132];
    const int tid = threadIdx.x;
    const int tx = tid & 15;        // 0..15  -> 8 cols each
    const int ty = tid >> 4;        // 0..15  -> 8 rows each
    const int row0 = blockIdx.y * 128;
    const int col0 = blockIdx.x * 128;

    const int ar = tid >> 1;          // 0..127  A row within tile
    const int ak = (tid & 1) * 4;     // 0 or 4  A k offset
    const int br = tid >> 5;          // 0..7    B k row
    const int bc = (tid & 31) * 4;    // 0..124  B col offset

    const float* Ap = A + (size_t)(row0 + ar) * K + ak;
    const float* Bp = Bm + (size_t)br * N + col0 + bc;

    float acc[8][8];
    #pragma unroll
    for (int u = 0; u < 8; u++)
        #pragma unroll
        for (int v = 0; v < 8; v++) acc[u][v] = 0.f;

    for (int k0 = 0; k0 < K; k0 += 8) {
        float4 av = *(const float4*)(Ap + k0);
        float4 bv = *(const float4*)(Bp + (size_t)k0 * N);
        As[ak + 0][ar] = av.x;
        As[ak + 1][ar] = av.y;
        As[ak + 2][ar] = av.z;
        As[ak + 3][ar] = av.w;
        *(float4*)&Bs[br][bc] = bv;
        __syncthreads();
        #pragma unroll
        for (int kk = 0; kk < 8; kk++) {
            float4 a0 = *(const float4*)&As[kk][ty * 8];
            float4 a1 = *(const float4*)&As[kk][ty * 8 + 4];
            float4 b0 = *(const float4*)&Bs[kk][tx * 8];
            float4 b1 = *(const float4*)&Bs[kk][tx * 8 + 4];
            float ra[8] = {a0.x, a0.y, a0.z, a0.w, a1.x, a1.y, a1.z, a1.w};
            float rb[8] = {b0.x, b0.y, b0.z, b0.w, b1.x, b1.y, b1.z, b1.w};
            #pragma unroll
            for (int u = 0; u < 8; u++)
                #pragma unroll
                for (int v = 0; v < 8; v++)
                    acc[u][v] += ra[u] * rb[v];
        }
        __syncthreads();
    }

    float bs[8];
    #pragma unroll
    for (int v = 0; v < 8; v++) bs[v] = bias[col0 + tx * 8 + v];

    #pragma unroll
    for (int u = 0; u < 8; u++) {
        int r = row0 + ty * 8 + u;
        float* Cp = C + (size_t)r * N + col0 + tx * 8;
        float4 o0, o1;
        float vv[8];
        #pragma unroll
        for (int v = 0; v < 8; v++) {
            float val = acc[u][v] + bs[v];
            if (RELU) val = fmaxf(val, 0.f);
            vv[v] = val;
        }
        o0.x = vv[0]; o0.y = vv[1]; o0.z = vv[2]; o0.w = vv[3];
        o1.x = vv[4]; o1.y = vv[5]; o1.z = vv[6]; o1.w = vv[7];
        *(float4*)Cp = o0;
        *(float4*)(Cp + 4) = o1;
    }
}

// ---------------- logits: L[bh,i,j] = (q_i . k_j)/8 - 1e9*mask[b,i,j] ----------------
// grid (S/64, S/64, BH), 256 threads, 64x64 tile, K=64 resident.
__global__ void __launch_bounds__(256) logits_kernel(
    const float* __restrict__ q, const float* __restrict__ kmat,
    const float* __restrict__ mask)
{
    const int bh = blockIdx.z;
    const int b = bh >> 3, h = bh & 7;
    const int i0 = blockIdx.y * 64, j0 = blockIdx.x * 64;

    __shared__ float Qs[64][68];   // [d][i]
    __shared__ float Ks[64][68];   // [d][j]

    const int tid = threadIdx.x;
    const int lc = tid & 63;       // d
    const int lr = tid >> 6;       // 0..3
    const float* qb = q + (size_t)(b * SS + i0) * DMODEL + h * 64;
    const float* kb = kmat + (size_t)(b * SS + j0) * DMODEL + h * 64;

    #pragma unroll
    for (int i = 0; i < 16; i++) {
        int r = lr * 16 + i;
        Qs[lc][r] = qb[(size_t)r * DMODEL + lc];
        Ks[lc][r] = kb[(size_t)r * DMODEL + lc];
    }
    __syncthreads();

    const int tx = tid & 15, ty = tid >> 4;
    float acc[4][4];
    #pragma unroll
    for (int u = 0; u < 4; u++)
        #pragma unroll
        for (int v = 0; v < 4; v++) acc[u][v] = 0.f;

    #pragma unroll
    for (int kk = 0; kk < 64; kk++) {
        float4 a = *(const float4*)&Qs[kk][ty * 4];
        float4 bv = *(const float4*)&Ks[kk][tx * 4];
        float ra[4] = {a.x, a.y, a.z, a.w};
        float rb[4] = {bv.x, bv.y, bv.z, bv.w};
        #pragma unroll
        for (int u = 0; u < 4; u++)
            #pragma unroll
            for (int v = 0; v < 4; v++)
                acc[u][v] += ra[u] * rb[v];
    }

    float* Lb = g_L + (size_t)bh * SS * SS;
    const float* mrow = mask + (size_t)b * SS * SS;
    #pragma unroll
    for (int u = 0; u < 4; u++) {
        int i = i0 + ty * 4 + u;
        const float4 mv = *(const float4*)&mrow[(size_t)i * SS + j0 + tx * 4];
        float4 ov;
        ov.x = acc[u][0] * 0.125f - 1e9f * mv.x;
        ov.y = acc[u][1] * 0.125f - 1e9f * mv.y;
        ov.z = acc[u][2] * 0.125f - 1e9f * mv.z;
        ov.w = acc[u][3] * 0.125f - 1e9f * mv.w;
        *(float4*)&Lb[(size_t)i * SS + j0 + tx * 4] = ov;
    }
}

// ---------------- softmax reduction: stage 1 (per-chunk online max/sumexp) ----------------
__global__ void __launch_bounds__(256) softmax_partial_kernel() {
    const int bh = blockIdx.y, cx = blockIdx.x, tid = threadIdx.x;
    const float* p = g_L + (size_t)bh * SS * SS + (size_t)cx * 8192;
    float m = -1e30f, s = 0.f;
    #pragma unroll 4
    for (int it = 0; it < 32; it++) {
        float x = p[it * 256 + tid];
        float nm = fmaxf(m, x);
        s = s * __expf(m - nm) + __expf(x - nm);
        m = nm;
    }
    __shared__ float sm[256], ss[256];
    sm[tid] = m; ss[tid] = s; __syncthreads();
    for (int off = 128; off; off >>= 1) {
        if (tid < off) {
            float m2 = sm[tid + off], s2 = ss[tid + off];
            float nm = fmaxf(sm[tid], m2);
            ss[tid] = ss[tid] * __expf(sm[tid] - nm) + s2 * __expf(m2 - nm);
            sm[tid] = nm;
        }
        __syncthreads();
    }
    if (tid == 0) {
        g_pm[bh * NCHUNK + cx] = sm[0];
        g_ps[bh * NCHUNK + cx] = ss[0];
    }
}

// ---------------- softmax reduction: stage 2 -> M[bh], scale[bh]=nz/Z ----------------
__global__ void __launch_bounds__(NCHUNK) softmax_final_kernel() {
    const int bh = blockIdx.x, tid = threadIdx.x;
    __shared__ float sm[NCHUNK], ss[NCHUNK];
    sm[tid] = g_pm[bh * NCHUNK + tid];
    ss[tid] = g_ps[bh * NCHUNK + tid];
    __syncthreads();
    for (int off = NCHUNK / 2; off; off >>= 1) {
        if (tid < off) {
            float m2 = sm[tid + off], s2 = ss[tid + off];
            float nm = fmaxf(sm[tid], m2);
            ss[tid] = ss[tid] * __expf(sm[tid] - nm) + s2 * __expf(m2 - nm);
            sm[tid] = nm;
        }
        __syncthreads();
    }
    if (tid == 0) {
        g_M[bh] = sm[0];
        g_scale[bh] = g_nz / ss[0];
    }
}

// ---------------- O[bh,i,d] = scale * sum_j exp(L[bh,j,i]-M) * V[b,j,h,d] ----------------
// grid (S/64, BH), 256 threads. Tile 64(i) x 64(d), K-chunks of 64 (j).
__global__ void __launch_bounds__(256) attnv_kernel(
    const float* __restrict__ v, float* __restrict__ o)
{
    const int bh = blockIdx.y;
    const int b = bh >> 3, h = bh & 7;
    const int i0 = blockIdx.x * 64;
    const float Mb = g_M[bh];
    const float sc = g_scale[bh];

    __shared__ float Ps[64][68];   // [j][i]
    __shared__ float Vs[64][68];   // [j][d]

    const int tid = threadIdx.x;
    const int lc = tid & 63;
    const int lr = tid >> 6;
    const int tx = tid & 15, ty = tid >> 4;

    const float* Lb = g_L + (size_t)bh * SS * SS;
    const float* vb = v + (size_t)b * SS * DMODEL + h * 64;

    float acc[4][4];
    #pragma unroll
    for (int u = 0; u < 4; u++)
        #pragma unroll
        for (int vv = 0; vv < 4; vv++) acc[u][vv] = 0.f;

    for (int j0 = 0; j0 < SS; j0 += 64) {
        #pragma unroll
        for (int i = 0; i < 16; i++) {
            int r = lr * 16 + i;    // j within tile
            Ps[r][lc] = __expf(Lb[(size_t)(j0 + r) * SS + i0 + lc] - Mb);
            Vs[r][lc] = vb[(size_t)(j0 + r) * DMODEL + lc];
        }
        __syncthreads();
        #pragma unroll
        for (int kk = 0; kk < 64; kk++) {
            float4 a = *(const float4*)&Ps[kk][ty * 4];
            float4 bv = *(const float4*)&Vs[kk][tx * 4];
            float ra[4] = {a.x, a.y, a.z, a.w};
            float rb[4] = {bv.x, bv.y, bv.z, bv.w};
            #pragma unroll
            for (int u = 0; u < 4; u++)
                #pragma unroll
                for (int vv = 0; vv < 4; vv++)
                    acc[u][vv] += ra[u] * rb[vv];
        }
        __syncthreads();
    }

    #pragma unroll
    for (int u = 0; u < 4; u++) {
        int i = i0 + ty * 4 + u;
        float4 ov;
        ov.x = acc[u][0] * sc;
        ov.y = acc[u][1] * sc;
        ov.z = acc[u][2] * sc;
        ov.w = acc[u][3] * sc;
        *(float4*)&o[(size_t)(b * SS + i) * DMODEL + h * 64 + tx * 4] = ov;
    }
}

// ---------------- out = LayerNorm(a + r) * gamma + beta ----------------
__global__ void __launch_bounds__(256) add_ln_kernel(
    const float* __restrict__ a, const float* __restrict__ r,
    const float* __restrict__ gam, const float* __restrict__ bet,
    float* __restrict__ o)
{
    __shared__ float red[256];
    const int row = blockIdx.x, t = threadIdx.x;
    const size_t base = (size_t)row * DMODEL;
    float y0 = a[base + t] + r[base + t];
    float y1 = a[base + t + 256] + r[base + t + 256];
    red[t] = y0 + y1; __syncthreads();
    for (int off = 128; off; off >>= 1) {
        if (t < off) red[t] += red[t + off];
        __syncthreads();
    }
    float mean = red[0] * (1.0f / DMODEL);
    __syncthreads();
    float d0 = y0 - mean, d1 = y1 - mean;
    red[t] = d0 * d0 + d1 * d1; __syncthreads();
    for (int off = 128; off; off >>= 1) {
        if (t < off) red[t] += red[t + off];
        __syncthreads();
    }
    float inv = rsqrtf(red[0] * (1.0f / DMODEL) + 1e-9f);
    o[base + t] = d0 * inv * gam[t] + bet[t];
    o[base + t + 256] = d1 * inv * gam[t + 256] + bet[t + 256];
}

// ---------------- host launcher ----------------
extern "C" void kernel_launch(void* const* d_in, const int* in_sizes, int n_in,
                              void* d_out, int out_size)
{
    (void)in_sizes; (void)n_in; (void)out_size;
    const float* x     = (const float*)d_in[0];
    const float* mask  = (const float*)d_in[1];
    const int*   ptk   = (const int*)d_in[2];
    const float* wq    = (const float*)d_in[3];
    const float* bq    = (const float*)d_in[4];
    const float* wk    = (const float*)d_in[5];
    const float* bk    = (const float*)d_in[6];
    const float* wv    = (const float*)d_in[7];
    const float* bv    = (const float*)d_in[8];
    const float* wo    = (const float*)d_in[9];
    const float* bo    = (const float*)d_in[10];
    const float* w1    = (const float*)d_in[11];
    const float* b1    = (const float*)d_in[12];
    const float* w2    = (const float*)d_in[13];
    const float* b2    = (const float*)d_in[14];
    const float* ln1g  = (const float*)d_in[15];
    const float* ln1b  = (const float*)d_in[16];
    const float* ln2g  = (const float*)d_in[17];
    const float* ln2b  = (const float*)d_in[18];
    float* out = (float*)d_out;

    float *q, *k, *v, *o, *t0, *out1, *ffn1, *hbuf;
    cudaGetSymbolAddress((void**)&q,    g_q);
    cudaGetSymbolAddress((void**)&k,    g_k);
    cudaGetSymbolAddress((void**)&v,    g_v);
    cudaGetSymbolAddress((void**)&o,    g_o);
    cudaGetSymbolAddress((void**)&t0,   g_t0);
    cudaGetSymbolAddress((void**)&out1, g_out1);
    cudaGetSymbolAddress((void**)&ffn1, g_ffn1);
    cudaGetSymbolAddress((void**)&hbuf, g_h);

    count_nz_kernel<<<1, 256>>>(ptk);

    const dim3 g512(DMODEL / 128, MROWS / 128);     // (4, 32)
    const dim3 gff(DFF / 128, MROWS / 128);         // (16, 32)
    const dim3 glog(SS / 64, SS / 64, BHTOT);       // (16, 16, 32)
    const dim3 gpart(NCHUNK, BHTOT);                // (128, 32)
    const dim3 gav(SS / 64, BHTOT);                 // (16, 32)

    const float* hin = x;
    for (int l = 0; l < 2; l++) {
        float* hout = (l == 1) ? out : hbuf;

        sgemm128<false><<<g512, 256>>>(hin, wq, bq, q, MROWS, DMODEL, DMODEL);
        sgemm128<false><<<g512, 256>>>(hin, wk, bk, k, MROWS, DMODEL, DMODEL);
        sgemm128<false><<<g512, 256>>>(hin, wv, bv, v, MROWS, DMODEL, DMODEL);

        logits_kernel<<<glog, 256>>>(q, k, mask);
        softmax_partial_kernel<<<gpart, 256>>>();
        softmax_final_kernel<<<BHTOT, NCHUNK>>>();
        attnv_kernel<<<gav, 256>>>(v, o);

        sgemm128<false><<<g512, 256>>>(o, wo, bo, t0, MROWS, DMODEL, DMODEL);
        add_ln_kernel<<<MROWS, 256>>>(hin, t0, ln1g, ln1b, out1);

        sgemm128<true><<<gff, 256>>>(out1, w1, b1, ffn1, MROWS, DFF, DMODEL);
        sgemm128<false><<<g512, 256>>>(ffn1, w2, b2, t0, MROWS, DMODEL, DFF);
        add_ln_kernel<<<MROWS, 256>>>(out1, t0, ln2g, ln2b, hout);

        hin = hout;
    }
}

// round 5
// speedup vs baseline: 2.5468x; 2.5468x over previous
#include <cuda_runtime.h>
#include <math.h>
#include <stddef.h>

#define BB     4
#define SS     1024
#define DMODEL 512
#define HH     8
#define DHEAD  64
#define DFF    2048
#define BHTOT  (BB*HH)          // 32
#define MROWS  (BB*SS)          // 4096
#define NCHUNK 64               // softmax partial chunks per (b,h) (8x8 logit blocks)

// ---------------- scratch (static device globals: alloc-free) ----------------
__device__ float g_L[(size_t)BHTOT * SS * SS];   // 128 MB logits
__device__ float g_q[MROWS * DMODEL];
__device__ float g_k[MROWS * DMODEL];
__device__ float g_v[MROWS * DMODEL];
__device__ float g_o[MROWS * DMODEL];
__device__ float g_t0[MROWS * DMODEL];
__device__ float g_out1[MROWS * DMODEL];
__device__ float g_ffn1[MROWS * DFF];
__device__ float g_h[MROWS * DMODEL];
__device__ float g_pm[BHTOT * NCHUNK];
__device__ float g_ps[BHTOT * NCHUNK];
__device__ float g_M[BHTOT];
__device__ float g_scale[BHTOT];
__device__ float g_nz;

// ---------------- helpers ----------------
__device__ __forceinline__ unsigned f2tf(float x) {
    unsigned r; asm("cvt.rna.tf32.f32 %0, %1;" : "=r"(r) : "f"(x)); return r;
}
__device__ __forceinline__ void mma_tf32(float c[4], const unsigned a[4], const unsigned b[2]) {
    asm volatile(
        "mma.sync.aligned.m16n8k8.row.col.f32.tf32.tf32.f32 "
        "{%0,%1,%2,%3}, {%4,%5,%6,%7}, {%8,%9}, {%0,%1,%2,%3};\n"
        : "+f"(c[0]), "+f"(c[1]), "+f"(c[2]), "+f"(c[3])
        : "r"(a[0]), "r"(a[1]), "r"(a[2]), "r"(a[3]), "r"(b[0]), "r"(b[1]));
}

// ---------------- count_nonzero(protok[0]) ----------------
__global__ void count_nz_kernel(const int* __restrict__ protok) {
    __shared__ int cnt[256];
    int t = threadIdx.x;
    int c = 0;
    for (int i = t; i < SS; i += 256) c += (protok[i] != 0);
    cnt[t] = c; __syncthreads();
    for (int off = 128; off; off >>= 1) {
        if (t < off) cnt[t] += cnt[t + off];
        __syncthreads();
    }
    if (t == 0) g_nz = (float)cnt[0];
}

// ---------------- tf32 tensor-core GEMM: C = act(A[4096xK] * B[KxN] + bias) ----------------
// 128x128 tile, BK=32, 256 threads (8 warps, 2x4), warp tile 64x32, m16n8k8.
// blockIdx.z selects one of up to 3 (B, bias, C) sets (fused QKV).
template <bool RELU>
__global__ void __launch_bounds__(256) gemm_tf32(
    const float* __restrict__ A,
    const float* __restrict__ B0, const float* __restrict__ bias0, float* __restrict__ C0,
    const float* __restrict__ B1, const float* __restrict__ bias1, float* __restrict__ C1,
    const float* __restrict__ B2, const float* __restrict__ bias2, float* __restrict__ C2,
    int N, int K)
{
    __shared__ unsigned As[128][36];     // [m][k], bank: (4m+k)%32 bijective
    __shared__ unsigned Bs[32][136];     // [k][n], bank: (8k+n)%32 bijective

    const float* Bm = B0; const float* bias = bias0; float* C = C0;
    if (blockIdx.z == 1) { Bm = B1; bias = bias1; C = C1; }
    else if (blockIdx.z == 2) { Bm = B2; bias = bias2; C = C2; }

    const int tid = threadIdx.x;
    const int wid = tid >> 5, lane = tid & 31;
    const int g = lane >> 2, t4 = lane & 3;
    const int warpM = wid & 1, warpN = wid >> 1;     // 2 x 4
    const int row0 = blockIdx.y * 128;
    const int col0 = blockIdx.x * 128;

    // global load mappings
    const int arow = tid >> 3;           // 0..31 (+i*32)
    const int acol = (tid & 7) * 4;
    const int brow = tid >> 5;           // 0..7 (+i*8)
    const int bcol = (tid & 31) * 4;

    float4 ra[4], rb[4];
    float acc[4][4][4];
    #pragma unroll
    for (int mi = 0; mi < 4; mi++)
        #pragma unroll
        for (int nj = 0; nj < 4; nj++)
            #pragma unroll
            for (int c = 0; c < 4; c++) acc[mi][nj][c] = 0.f;

    auto loadG = [&](int k0) {
        #pragma unroll
        for (int i = 0; i < 4; i++)
            ra[i] = *(const float4*)(A + (size_t)(row0 + arow + i * 32) * K + k0 + acol);
        #pragma unroll
        for (int i = 0; i < 4; i++)
            rb[i] = *(const float4*)(Bm + (size_t)(k0 + brow + i * 8) * N + col0 + bcol);
    };
    auto storeS = [&]() {
        #pragma unroll
        for (int i = 0; i < 4; i++) {
            uint4 u;
            u.x = f2tf(ra[i].x); u.y = f2tf(ra[i].y); u.z = f2tf(ra[i].z); u.w = f2tf(ra[i].w);
            *(uint4*)&As[arow + i * 32][acol] = u;
        }
        #pragma unroll
        for (int i = 0; i < 4; i++) {
            uint4 u;
            u.x = f2tf(rb[i].x); u.y = f2tf(rb[i].y); u.z = f2tf(rb[i].z); u.w = f2tf(rb[i].w);
            *(uint4*)&Bs[brow + i * 8][bcol] = u;
        }
    };

    loadG(0); storeS(); __syncthreads();

    for (int k0 = 0; k0 < K; k0 += 32) {
        const bool more = (k0 + 32) < K;
        if (more) loadG(k0 + 32);
        #pragma unroll
        for (int ks = 0; ks < 4; ks++) {
            const int kb = ks * 8;
            unsigned afr[4][4], bfr[4][2];
            #pragma unroll
            for (int mi = 0; mi < 4; mi++) {
                const int rm = warpM * 64 + mi * 16;
                afr[mi][0] = As[rm + g][kb + t4];
                afr[mi][1] = As[rm + g + 8][kb + t4];
                afr[mi][2] = As[rm + g][kb + t4 + 4];
                afr[mi][3] = As[rm + g + 8][kb + t4 + 4];
            }
            #pragma unroll
            for (int nj = 0; nj < 4; nj++) {
                const int cn = warpN * 32 + nj * 8;
                bfr[nj][0] = Bs[kb + t4][cn + g];
                bfr[nj][1] = Bs[kb + t4 + 4][cn + g];
            }
            #pragma unroll
            for (int mi = 0; mi < 4; mi++)
                #pragma unroll
                for (int nj = 0; nj < 4; nj++)
                    mma_tf32(acc[mi][nj], afr[mi], bfr[nj]);
        }
        __syncthreads();
        if (more) { storeS(); __syncthreads(); }
    }

    // epilogue
    #pragma unroll
    for (int mi = 0; mi < 4; mi++) {
        const int r = row0 + warpM * 64 + mi * 16 + g;
        #pragma unroll
        for (int nj = 0; nj < 4; nj++) {
            const int c = col0 + warpN * 32 + nj * 8 + 2 * t4;
            const float b0 = bias[c], b1 = bias[c + 1];
            float v0 = acc[mi][nj][0] + b0, v1 = acc[mi][nj][1] + b1;
            float v2 = acc[mi][nj][2] + b0, v3 = acc[mi][nj][3] + b1;
            if (RELU) {
                v0 = fmaxf(v0, 0.f); v1 = fmaxf(v1, 0.f);
                v2 = fmaxf(v2, 0.f); v3 = fmaxf(v3, 0.f);
            }
            float2 p0; p0.x = v0; p0.y = v1;
            float2 p1; p1.x = v2; p1.y = v3;
            *(float2*)&C[(size_t)r * N + c] = p0;
            *(float2*)&C[(size_t)(r + 8) * N + c] = p1;
        }
    }
}

// ---------------- logits (fp32, precision-critical) + fused softmax partials ----------------
// L[bh,i,j] = (q_i . k_j)/8 - 1e9*mask[b,i,j].  128x128 tile, 8x8/thread, BK=32.
// Epilogue reduces the block's (max, sumexp) partial to g_pm/g_ps.
__global__ void __launch_bounds__(256) logits128(
    const float* __restrict__ q, const float* __restrict__ kmat,
    const float* __restrict__ mask)
{
    __shared__ float Qs[32][132];    // [d][i]
    __shared__ float Ks[32][132];    // [d][j]
    __shared__ float red_m[256], red_s[256];

    const int bh = blockIdx.z, b = bh >> 3, h = bh & 7;
    const int i0 = blockIdx.y * 128, j0 = blockIdx.x * 128;
    const int tid = threadIdx.x;
    const int tx = tid & 15, ty = tid >> 4;

    const float* qb = q + (size_t)(b * SS + i0) * DMODEL + h * 64;
    const float* kb = kmat + (size_t)(b * SS + j0) * DMODEL + h * 64;

    float acc[8][8];
    #pragma unroll
    for (int u = 0; u < 8; u++)
        #pragma unroll
        for (int v = 0; v < 8; v++) acc[u][v] = 0.f;

    const int r = tid >> 3;           // 0..31
    const int d4 = (tid & 7) * 4;

    for (int k0 = 0; k0 < 64; k0 += 32) {
        #pragma unroll
        for (int it = 0; it < 4; it++) {
            const int i = r + it * 32;
            float4 qv = *(const float4*)(qb + (size_t)i * DMODEL + k0 + d4);
            Qs[d4 + 0][i] = qv.x; Qs[d4 + 1][i] = qv.y;
            Qs[d4 + 2][i] = qv.z; Qs[d4 + 3][i] = qv.w;
            float4 kv = *(const float4*)(kb + (size_t)i * DMODEL + k0 + d4);
            Ks[d4 + 0][i] = kv.x; Ks[d4 + 1][i] = kv.y;
            Ks[d4 + 2][i] = kv.z; Ks[d4 + 3][i] = kv.w;
        }
        __syncthreads();
        #pragma unroll
        for (int kk = 0; kk < 32; kk++) {
            float4 a0 = *(const float4*)&Qs[kk][ty * 8];
            float4 a1 = *(const float4*)&Qs[kk][ty * 8 + 4];
            float4 b0 = *(const float4*)&Ks[kk][tx * 8];
            float4 b1 = *(const float4*)&Ks[kk][tx * 8 + 4];
            float rA[8] = {a0.x, a0.y, a0.z, a0.w, a1.x, a1.y, a1.z, a1.w};
            float rB[8] = {b0.x, b0.y, b0.z, b0.w, b1.x, b1.y, b1.z, b1.w};
            #pragma unroll
            for (int u = 0; u < 8; u++)
                #pragma unroll
                for (int v = 0; v < 8; v++)
                    acc[u][v] += rA[u] * rB[v];
        }
        __syncthreads();
    }

    // epilogue: scale, mask, store L, track per-thread (max, sumexp)
    float* Lb = g_L + (size_t)bh * SS * SS;
    const float* mrow = mask + (size_t)b * SS * SS;
    #pragma unroll
    for (int u = 0; u < 8; u++) {
        const int i = i0 + ty * 8 + u;
        #pragma unroll
        for (int v4 = 0; v4 < 2; v4++) {
            const int j = j0 + tx * 8 + v4 * 4;
            const float4 mv = *(const float4*)&mrow[(size_t)i * SS + j];
            float4 ov;
            ov.x = acc[u][v4 * 4 + 0] * 0.125f - 1e9f * mv.x;
            ov.y = acc[u][v4 * 4 + 1] * 0.125f - 1e9f * mv.y;
            ov.z = acc[u][v4 * 4 + 2] * 0.125f - 1e9f * mv.z;
            ov.w = acc[u][v4 * 4 + 3] * 0.125f - 1e9f * mv.w;
            acc[u][v4 * 4 + 0] = ov.x; acc[u][v4 * 4 + 1] = ov.y;
            acc[u][v4 * 4 + 2] = ov.z; acc[u][v4 * 4 + 3] = ov.w;
            *(float4*)&Lb[(size_t)i * SS + j] = ov;
        }
    }
    float pm = -1e30f;
    #pragma unroll
    for (int u = 0; u < 8; u++)
        #pragma unroll
        for (int v = 0; v < 8; v++) pm = fmaxf(pm, acc[u][v]);
    float psum = 0.f;
    #pragma unroll
    for (int u = 0; u < 8; u++)
        #pragma unroll
        for (int v = 0; v < 8; v++) psum += __expf(acc[u][v] - pm);

    red_m[tid] = pm; red_s[tid] = psum; __syncthreads();
    for (int off = 128; off; off >>= 1) {
        if (tid < off) {
            float m2 = red_m[tid + off], s2 = red_s[tid + off];
            float nm = fmaxf(red_m[tid], m2);
            red_s[tid] = red_s[tid] * __expf(red_m[tid] - nm) + s2 * __expf(m2 - nm);
            red_m[tid] = nm;
        }
        __syncthreads();
    }
    if (tid == 0) {
        const int cid = blockIdx.y * 8 + blockIdx.x;
        g_pm[bh * NCHUNK + cid] = red_m[0];
        g_ps[bh * NCHUNK + cid] = red_s[0];
    }
}

// ---------------- softmax final: M[bh], scale[bh] = nz/Z ----------------
__global__ void __launch_bounds__(NCHUNK) softmax_final_kernel() {
    const int bh = blockIdx.x, tid = threadIdx.x;
    __shared__ float sm[NCHUNK], ss[NCHUNK];
    sm[tid] = g_pm[bh * NCHUNK + tid];
    ss[tid] = g_ps[bh * NCHUNK + tid];
    __syncthreads();
    for (int off = NCHUNK / 2; off; off >>= 1) {
        if (tid < off) {
            float m2 = sm[tid + off], s2 = ss[tid + off];
            float nm = fmaxf(sm[tid], m2);
            ss[tid] = ss[tid] * __expf(sm[tid] - nm) + s2 * __expf(m2 - nm);
            sm[tid] = nm;
        }
        __syncthreads();
    }
    if (tid == 0) {
        g_M[bh] = sm[0];
        g_scale[bh] = g_nz / ss[0];
    }
}

// ---------------- attnv (tf32 mma): O[bh,i,d] = sc * sum_j exp(L[j,i]-M) * V[b,j,h,d] ----------------
// Block: 128 i-rows x 64 d-cols, K(j) tiles of 32. 8 warps (2x4), warp tile 64x16.
__global__ void __launch_bounds__(256) attnv_tf32(
    const float* __restrict__ v, float* __restrict__ o)
{
    __shared__ unsigned Ps[32][132];   // [j][i]  (A^T: exactly mma's [k][m])
    __shared__ unsigned Vs[32][72];    // [j][d]

    const int bh = blockIdx.y, b = bh >> 3, h = bh & 7;
    const int i0 = blockIdx.x * 128;
    const float Mb = g_M[bh], sc = g_scale[bh];

    const int tid = threadIdx.x;
    const int wid = tid >> 5, lane = tid & 31;
    const int g = lane >> 2, t4 = lane & 3;
    const int warpM = wid & 1, warpN = wid >> 1;

    const float* Lb = g_L + (size_t)bh * SS * SS;
    const float* vb = v + (size_t)b * SS * DMODEL + h * 64;

    float acc[4][2][4];
    #pragma unroll
    for (int mi = 0; mi < 4; mi++)
        #pragma unroll
        for (int nj = 0; nj < 2; nj++)
            #pragma unroll
            for (int c = 0; c < 4; c++) acc[mi][nj][c] = 0.f;

    const int pr = tid >> 3;          // j row 0..31
    const int pc4 = (tid & 7) * 4;    // i col, + it*32
    float4 rp[4]; float4 rv[2];

    auto loadG = [&](int j0) {
        #pragma unroll
        for (int it = 0; it < 4; it++)
            rp[it] = *(const float4*)(Lb + (size_t)(j0 + pr) * SS + i0 + pc4 + it * 32);
        #pragma unroll
        for (int it = 0; it < 2; it++)
            rv[it] = *(const float4*)(vb + (size_t)(j0 + pr) * DMODEL + pc4 + it * 32);
    };
    auto storeS = [&]() {
        #pragma unroll
        for (int it = 0; it < 4; it++) {
            uint4 u;
            u.x = f2tf(__expf(rp[it].x - Mb));
            u.y = f2tf(__expf(rp[it].y - Mb));
            u.z = f2tf(__expf(rp[it].z - Mb));
            u.w = f2tf(__expf(rp[it].w - Mb));
            *(uint4*)&Ps[pr][pc4 + it * 32] = u;
        }
        #pragma unroll
        for (int it = 0; it < 2; it++) {
            uint4 u;
            u.x = f2tf(rv[it].x); u.y = f2tf(rv[it].y);
            u.z = f2tf(rv[it].z); u.w = f2tf(rv[it].w);
            *(uint4*)&Vs[pr][pc4 + it * 32] = u;
        }
    };

    loadG(0); storeS(); __syncthreads();

    for (int j0 = 0; j0 < SS; j0 += 32) {
        const bool more = (j0 + 32) < SS;
        if (more) loadG(j0 + 32);
        #pragma unroll
        for (int ks = 0; ks < 4; ks++) {
            const int kb = ks * 8;
            unsigned afr[4][4], bfr[2][2];
            #pragma unroll
            for (int mi = 0; mi < 4; mi++) {
                const int rm = warpM * 64 + mi * 16;
                afr[mi][0] = Ps[kb + t4][rm + g];
                afr[mi][1] = Ps[kb + t4][rm + g + 8];
                afr[mi][2] = Ps[kb + t4 + 4][rm + g];
                afr[mi][3] = Ps[kb + t4 + 4][rm + g + 8];
            }
            #pragma unroll
            for (int nj = 0; nj < 2; nj++) {
                const int cn = warpN * 16 + nj * 8;
                bfr[nj][0] = Vs[kb + t4][cn + g];
                bfr[nj][1] = Vs[kb + t4 + 4][cn + g];
            }
            #pragma unroll
            for (int mi = 0; mi < 4; mi++)
                #pragma unroll
                for (int nj = 0; nj < 2; nj++)
                    mma_tf32(acc[mi][nj], afr[mi], bfr[nj]);
        }
        __syncthreads();
        if (more) { storeS(); __syncthreads(); }
    }

    #pragma unroll
    for (int mi = 0; mi < 4; mi++) {
        const int i = i0 + warpM * 64 + mi * 16 + g;
        #pragma unroll
        for (int nj = 0; nj < 2; nj++) {
            const int c = warpN * 16 + nj * 8 + 2 * t4;
            float2 p0; p0.x = acc[mi][nj][0] * sc; p0.y = acc[mi][nj][1] * sc;
            float2 p1; p1.x = acc[mi][nj][2] * sc; p1.y = acc[mi][nj][3] * sc;
            *(float2*)&o[(size_t)(b * SS + i) * DMODEL + h * 64 + c] = p0;
            *(float2*)&o[(size_t)(b * SS + i + 8) * DMODEL + h * 64 + c] = p1;
        }
    }
}

// ---------------- out = LayerNorm(a + r) * gamma + beta ----------------
__global__ void __launch_bounds__(256) add_ln_kernel(
    const float* __restrict__ a, const float* __restrict__ r,
    const float* __restrict__ gam, const float* __restrict__ bet,
    float* __restrict__ o)
{
    __shared__ float red[256];
    const int row = blockIdx.x, t = threadIdx.x;
    const size_t base = (size_t)row * DMODEL;
    float y0 = a[base + t] + r[base + t];
    float y1 = a[base + t + 256] + r[base + t + 256];
    red[t] = y0 + y1; __syncthreads();
    for (int off = 128; off; off >>= 1) {
        if (t < off) red[t] += red[t + off];
        __syncthreads();
    }
    float mean = red[0] * (1.0f / DMODEL);
    __syncthreads();
    float d0 = y0 - mean, d1 = y1 - mean;
    red[t] = d0 * d0 + d1 * d1; __syncthreads();
    for (int off = 128; off; off >>= 1) {
        if (t < off) red[t] += red[t + off];
        __syncthreads();
    }
    float inv = rsqrtf(red[0] * (1.0f / DMODEL) + 1e-9f);
    o[base + t] = d0 * inv * gam[t] + bet[t];
    o[base + t + 256] = d1 * inv * gam[t + 256] + bet[t + 256];
}

// ---------------- host launcher ----------------
extern "C" void kernel_launch(void* const* d_in, const int* in_sizes, int n_in,
                              void* d_out, int out_size)
{
    (void)in_sizes; (void)n_in; (void)out_size;
    const float* x     = (const float*)d_in[0];
    const float* mask  = (const float*)d_in[1];
    const int*   ptk   = (const int*)d_in[2];
    const float* wq    = (const float*)d_in[3];
    const float* bq    = (const float*)d_in[4];
    const float* wk    = (const float*)d_in[5];
    const float* bk    = (const float*)d_in[6];
    const float* wv    = (const float*)d_in[7];
    const float* bv    = (const float*)d_in[8];
    const float* wo    = (const float*)d_in[9];
    const float* bo    = (const float*)d_in[10];
    const float* w1    = (const float*)d_in[11];
    const float* b1    = (const float*)d_in[12];
    const float* w2    = (const float*)d_in[13];
    const float* b2    = (const float*)d_in[14];
    const float* ln1g  = (const float*)d_in[15];
    const float* ln1b  = (const float*)d_in[16];
    const float* ln2g  = (const float*)d_in[17];
    const float* ln2b  = (const float*)d_in[18];
    float* out = (float*)d_out;

    float *q, *k, *v, *o, *t0, *out1, *ffn1, *hbuf;
    cudaGetSymbolAddress((void**)&q,    g_q);
    cudaGetSymbolAddress((void**)&k,    g_k);
    cudaGetSymbolAddress((void**)&v,    g_v);
    cudaGetSymbolAddress((void**)&o,    g_o);
    cudaGetSymbolAddress((void**)&t0,   g_t0);
    cudaGetSymbolAddress((void**)&out1, g_out1);
    cudaGetSymbolAddress((void**)&ffn1, g_ffn1);
    cudaGetSymbolAddress((void**)&hbuf, g_h);

    count_nz_kernel<<<1, 256>>>(ptk);

    const dim3 gqkv(DMODEL / 128, MROWS / 128, 3);   // (4, 32, 3)
    const dim3 g512(DMODEL / 128, MROWS / 128, 1);   // (4, 32)
    const dim3 gff(DFF / 128, MROWS / 128, 1);       // (16, 32)
    const dim3 glog(SS / 128, SS / 128, BHTOT);      // (8, 8, 32)
    const dim3 gav(SS / 128, BHTOT);                 // (8, 32)

    const float* hin = x;
    for (int l = 0; l < 2; l++) {
        float* hout = (l == 1) ? out : hbuf;

        gemm_tf32<false><<<gqkv, 256>>>(hin,
            wq, bq, q,  wk, bk, k,  wv, bv, v,  DMODEL, DMODEL);

        logits128<<<glog, 256>>>(q, k, mask);
        softmax_final_kernel<<<BHTOT, NCHUNK>>>();
        attnv_tf32<<<gav, 256>>>(v, o);

        gemm_tf32<false><<<g512, 256>>>(o,
            wo, bo, t0,  wo, bo, t0,  wo, bo, t0,  DMODEL, DMODEL);
        add_ln_kernel<<<MROWS, 256>>>(hin, t0, ln1g, ln1b, out1);

        gemm_tf32<true><<<gff, 256>>>(out1,
            w1, b1, ffn1,  w1, b1, ffn1,  w1, b1, ffn1,  DFF, DMODEL);
        gemm_tf32<false><<<g512, 256>>>(ffn1,
            w2, b2, t0,  w2, b2, t0,  w2, b2, t0,  DMODEL, DFF);
        add_ln_kernel<<<MROWS, 256>>>(out1, t0, ln2g, ln2b, hout);

        hin = hout;
    }
}